// round 15
// baseline (speedup 1.0000x reference)
#include <cuda_runtime.h>
#include <cuda_fp16.h>
#include <math.h>
#include <stdint.h>

// ---------------- problem constants ----------------
constexpr int kH     = 2048;
constexpr int kL     = 512;
constexpr int kN     = 2048;
constexpr int kSEQ   = 2560;
constexpr int kHEADS = 16;
constexpr int kHD    = 128;
constexpr int kMLP   = 8192;

// ---------------- scratch (float + half pools, no allocs) ----------------
constexpr size_t FOFF_SILU = 0;
constexpr size_t FOFF_MOD  = FOFF_SILU + kH;
constexpr size_t FOFF_RES  = FOFF_MOD + (size_t)2 * 6 * kH;
constexpr size_t FTOT      = FOFF_RES + (size_t)kSEQ * kH;

constexpr size_t HOFF_XN   = 0;
constexpr size_t HOFF_QKV  = HOFF_XN  + (size_t)kSEQ * kH;
constexpr size_t HOFF_Q    = HOFF_QKV + (size_t)kSEQ * 3 * kH;
constexpr size_t HOFF_K    = HOFF_Q   + (size_t)kHEADS * kSEQ * kHD;
constexpr size_t HOFF_VT   = HOFF_K   + (size_t)kHEADS * kSEQ * kHD;
constexpr size_t HOFF_AO   = HOFF_VT  + (size_t)kHEADS * kHD * kSEQ;
constexpr size_t HOFF_H1   = HOFF_AO  + (size_t)kSEQ * kH;           // [kSEQ][kMLP], txt rows first
constexpr size_t HOFF_WQT  = HOFF_H1  + (size_t)kSEQ * kMLP;
constexpr size_t HOFF_WQI  = HOFF_WQT + (size_t)3 * kH * kH;
constexpr size_t HOFF_WOT  = HOFF_WQI + (size_t)3 * kH * kH;
constexpr size_t HOFF_WOI  = HOFF_WOT + (size_t)kH * kH;
constexpr size_t HOFF_W1T  = HOFF_WOI + (size_t)kH * kH;
constexpr size_t HOFF_W1I  = HOFF_W1T + (size_t)kMLP * kH;
constexpr size_t HOFF_W2T  = HOFF_W1I + (size_t)kMLP * kH;
constexpr size_t HOFF_W2I  = HOFF_W2T + (size_t)kH * kMLP;
constexpr size_t HTOT      = HOFF_W2I + (size_t)kH * kMLP;

__device__ __align__(256) float  g_scratch_f[FTOT];
__device__ __align__(256) __half g_scratch_h[HTOT];

// ---------------- small helper kernels ----------------
__global__ void silu_kernel(const float* __restrict__ vec, float* __restrict__ out) {
    int i = blockIdx.x * blockDim.x + threadIdx.x;
    if (i < kH) {
        float v = vec[i];
        out[i] = v / (1.f + expf(-v));
    }
}

__global__ void adaln_gemv(const float* __restrict__ silu,
                           const float* __restrict__ tw, const float* __restrict__ tb,
                           const float* __restrict__ iw, const float* __restrict__ ib,
                           float* __restrict__ mod) {
    int gw = (blockIdx.x * blockDim.x + threadIdx.x) >> 5;
    int lane = threadIdx.x & 31;
    if (gw >= 2 * 6 * kH) return;
    int set = gw / (6 * kH);
    int o = gw - set * (6 * kH);
    const float* W = (set ? iw : tw) + (size_t)o * kH;
    float s = 0.f;
    for (int i = lane; i < kH; i += 32) s += silu[i] * W[i];
    #pragma unroll
    for (int off = 16; off; off >>= 1) s += __shfl_xor_sync(0xffffffffu, s, off);
    if (lane == 0) mod[(size_t)set * 6 * kH + o] = s + (set ? ib[o] : tb[o]);
}

__global__ void f2h(const float4* __restrict__ in, __half2* __restrict__ out, int n4) {
    int i = blockIdx.x * blockDim.x + threadIdx.x;
    if (i >= n4) return;
    float4 v = in[i];
    out[2 * i + 0] = __floats2half2_rn(v.x, v.y);
    out[2 * i + 1] = __floats2half2_rn(v.z, v.w);
}

// merged norm+modulate over 2560 rows; row<msplit -> side 0 params.
__global__ void norm_mod2(const float* __restrict__ x0, const float* __restrict__ x1,
                          __half* __restrict__ out,
                          const float* __restrict__ w0, const float* __restrict__ w1,
                          const float* __restrict__ sh0, const float* __restrict__ sc0,
                          const float* __restrict__ sh1, const float* __restrict__ sc1,
                          int msplit) {
    int row = blockIdx.x;
    bool side = row >= msplit;
    const float* xr = side ? x1 + (size_t)(row - msplit) * kH : x0 + (size_t)row * kH;
    const float* w  = side ? w1 : w0;
    const float* sh = side ? sh1 : sh0;
    const float* sc = side ? sc1 : sc0;
    __half* orow = out + (size_t)row * kH;
    int tid = threadIdx.x;
    float ss = 0.f;
    for (int i = tid; i < kH; i += 256) { float v = xr[i]; ss += v * v; }
    __shared__ float sred[8];
    #pragma unroll
    for (int off = 16; off; off >>= 1) ss += __shfl_xor_sync(0xffffffffu, ss, off);
    if ((tid & 31) == 0) sred[tid >> 5] = ss;
    __syncthreads();
    if (tid < 8) {
        float v = sred[tid];
        #pragma unroll
        for (int off = 4; off; off >>= 1) v += __shfl_xor_sync(0xffu, v, off);
        if (tid == 0) sred[0] = v;
    }
    __syncthreads();
    float norm = rsqrtf(sred[0] * (1.f / kH) + 1e-6f);
    for (int i = tid; i < kH; i += 256)
        orow[i] = __float2half_rn(xr[i] * norm * w[i] * (1.f + sc[i]) + sh[i]);
}

__global__ void rope_scatter(const __half* __restrict__ qkv, const float* __restrict__ rope,
                             __half* __restrict__ q, __half* __restrict__ k,
                             __half* __restrict__ vt) {
    int gid = blockIdx.x * blockDim.x + threadIdx.x;
    if (gid >= kSEQ * kHEADS * (kHD / 2)) return;
    int j = gid & 63;
    int h = (gid >> 6) & 15;
    int n = gid >> 10;
    int d = j * 2;
    const float qscale = 0.08838834764831845f;
    const __half* base = qkv + (size_t)n * 3 * kH;
    float2 qv = __half22float2(*(const __half2*)(base + h * kHD + d));
    float2 kv = __half22float2(*(const __half2*)(base + kH + h * kHD + d));
    float2 vv = __half22float2(*(const __half2*)(base + 2 * kH + h * kHD + d));
    float q0 = qv.x, q1 = qv.y, k0 = kv.x, k1 = kv.y;
    if (n >= kL) {
        const float* r = rope + (size_t)(n - kL) * kHD + d;
        float c = r[0], s = r[1];
        float t;
        t = q0 * c - q1 * s; q1 = q1 * c + q0 * s; q0 = t;
        t = k0 * c - k1 * s; k1 = k1 * c + k0 * s; k0 = t;
    }
    size_t qi = ((size_t)h * kSEQ + n) * kHD + d;
    *(__half2*)(q + qi) = __floats2half2_rn(q0 * qscale, q1 * qscale);
    *(__half2*)(k + qi) = __floats2half2_rn(k0, k1);
    size_t vi = ((size_t)h * kHD + d) * kSEQ + n;
    vt[vi] = __float2half_rn(vv.x);
    vt[vi + kSEQ] = __float2half_rn(vv.y);
}

// ---------------- shared mma/ldmatrix/cp.async helpers ----------------
__device__ __forceinline__ float gelu_tanh(float x) {
    float x3 = x * x * x;
    return 0.5f * x * (1.f + tanhf(0.7978845608028654f * (x + 0.044715f * x3)));
}

__device__ __forceinline__ uint32_t pack_half2(float lo, float hi) {
    uint32_t r;
    asm("cvt.rn.f16x2.f32 %0, %1, %2;" : "=r"(r) : "f"(hi), "f"(lo));
    return r;
}

__device__ __forceinline__ void mma_f16(float c[4], const uint32_t a[4],
                                        uint32_t b0, uint32_t b1) {
    asm volatile(
        "mma.sync.aligned.m16n8k16.row.col.f32.f16.f16.f32 "
        "{%0,%1,%2,%3}, {%4,%5,%6,%7}, {%8,%9}, {%0,%1,%2,%3};\n"
        : "+f"(c[0]), "+f"(c[1]), "+f"(c[2]), "+f"(c[3])
        : "r"(a[0]), "r"(a[1]), "r"(a[2]), "r"(a[3]), "r"(b0), "r"(b1));
}

__device__ __forceinline__ void ldsm4(uint32_t& r0, uint32_t& r1, uint32_t& r2,
                                      uint32_t& r3, const uint32_t* p) {
    uint32_t a = (uint32_t)__cvta_generic_to_shared(p);
    asm volatile("ldmatrix.sync.aligned.m8n8.x4.shared.b16 {%0,%1,%2,%3}, [%4];\n"
                 : "=r"(r0), "=r"(r1), "=r"(r2), "=r"(r3) : "r"(a));
}

__device__ __forceinline__ void cp16(uint32_t* smem_dst, const void* gsrc) {
    uint32_t s = (uint32_t)__cvta_generic_to_shared(smem_dst);
    asm volatile("cp.async.cg.shared.global [%0], [%1], 16;\n" :: "r"(s), "l"(gsrc));
}

// ================= fused flash attention (R12 config) ======================
constexpr int FA_PITCH = 84;
constexpr int FA_TILE  = 128 * FA_PITCH;
constexpr size_t FA_SMEM = (size_t)4 * FA_TILE * 4;  // 172032 B

__global__ __launch_bounds__(256, 1) void flash_attn(
    const __half* __restrict__ q, const __half* __restrict__ k,
    const __half* __restrict__ vt, __half* __restrict__ ao)
{
    int qb = blockIdx.x, head = blockIdx.y;
    extern __shared__ uint32_t sm[];
    uint32_t* Ks = sm;
    uint32_t* Vs = sm + 2 * FA_TILE;

    int tid = threadIdx.x, wid = tid >> 5, lane = tid & 31;
    int qd = lane >> 2, s = lane & 3;

    const __half* kgb = k  + (size_t)head * kSEQ * kHD;
    const __half* vgb = vt + (size_t)head * kHD * kSEQ;

    const __half* qg = q + ((size_t)head * kSEQ + qb * 128 + wid * 16) * kHD;
    uint32_t qfrag[8][4];
    #pragma unroll
    for (int kg = 0; kg < 8; kg++) {
        qfrag[kg][0] = *(const uint32_t*)(qg + (size_t)qd * kHD + kg * 16 + 2 * s);
        qfrag[kg][1] = *(const uint32_t*)(qg + (size_t)(qd + 8) * kHD + kg * 16 + 2 * s);
        qfrag[kg][2] = *(const uint32_t*)(qg + (size_t)qd * kHD + kg * 16 + 8 + 2 * s);
        qfrag[kg][3] = *(const uint32_t*)(qg + (size_t)(qd + 8) * kHD + kg * 16 + 8 + 2 * s);
    }

    auto fill = [&](int j, int st) {
        const __half* kj = kgb + (size_t)j * 128 * kHD;
        const __half* vj = vgb + j * 128;
        uint32_t* ks = Ks + st * FA_TILE;
        uint32_t* vs = Vs + st * FA_TILE;
        #pragma unroll
        for (int i = 0; i < 8; i++) {
            int u = tid + i * 256;
            int row = u >> 4, w16 = u & 15;
            int sw = row * FA_PITCH + (w16 >> 2) * 20 + (w16 & 3) * 4;
            cp16(ks + sw, kj + (size_t)row * kHD + w16 * 8);
            cp16(vs + sw, vj + (size_t)row * kSEQ + w16 * 8);
        }
    };

    float oacc[16][4] = {};
    float m0 = -3.0e38f, m1 = -3.0e38f, l0 = 0.f, l1 = 0.f;

    int b_rsub = ((lane >> 4) * 8) + (lane & 7);
    int b_ksub = ((lane >> 3) & 1) * 4;

    fill(0, 0);
    asm volatile("cp.async.commit_group;\n");

    constexpr int NJ = kSEQ / 128;
    for (int j = 0; j < NJ; j++) {
        int st = j & 1;
        if (j + 1 < NJ) {
            fill(j + 1, st ^ 1);
            asm volatile("cp.async.commit_group;\n");
            asm volatile("cp.async.wait_group 1;\n");
        } else {
            asm volatile("cp.async.wait_group 0;\n");
        }
        __syncthreads();

        const uint32_t* ks = Ks + st * FA_TILE;
        const uint32_t* vs = Vs + st * FA_TILE;

        float sacc[16][4] = {};
        #pragma unroll
        for (int kg = 0; kg < 8; kg++) {
            int woff = (kg >> 1) * 20 + (kg & 1) * 8 + b_ksub;
            uint32_t bfr[16][2];
            #pragma unroll
            for (int tp = 0; tp < 8; tp++) {
                int row = tp * 16 + b_rsub;
                ldsm4(bfr[2 * tp][0], bfr[2 * tp][1],
                      bfr[2 * tp + 1][0], bfr[2 * tp + 1][1],
                      ks + row * FA_PITCH + woff);
            }
            #pragma unroll
            for (int tn = 0; tn < 16; tn++)
                mma_f16(sacc[tn], qfrag[kg], bfr[tn][0], bfr[tn][1]);
        }

        float mb0 = -3.0e38f, mb1 = -3.0e38f;
        #pragma unroll
        for (int tn = 0; tn < 16; tn++) {
            mb0 = fmaxf(mb0, fmaxf(sacc[tn][0], sacc[tn][1]));
            mb1 = fmaxf(mb1, fmaxf(sacc[tn][2], sacc[tn][3]));
        }
        mb0 = fmaxf(mb0, __shfl_xor_sync(0xffffffffu, mb0, 1));
        mb0 = fmaxf(mb0, __shfl_xor_sync(0xffffffffu, mb0, 2));
        mb1 = fmaxf(mb1, __shfl_xor_sync(0xffffffffu, mb1, 1));
        mb1 = fmaxf(mb1, __shfl_xor_sync(0xffffffffu, mb1, 2));
        float mn0 = fmaxf(m0, mb0), mn1 = fmaxf(m1, mb1);
        float sc0 = __expf(m0 - mn0), sc1 = __expf(m1 - mn1);
        float rs0 = 0.f, rs1 = 0.f;
        #pragma unroll
        for (int tn = 0; tn < 16; tn++) {
            sacc[tn][0] = __expf(sacc[tn][0] - mn0);
            sacc[tn][1] = __expf(sacc[tn][1] - mn0);
            sacc[tn][2] = __expf(sacc[tn][2] - mn1);
            sacc[tn][3] = __expf(sacc[tn][3] - mn1);
            rs0 += sacc[tn][0] + sacc[tn][1];
            rs1 += sacc[tn][2] + sacc[tn][3];
        }
        rs0 += __shfl_xor_sync(0xffffffffu, rs0, 1);
        rs0 += __shfl_xor_sync(0xffffffffu, rs0, 2);
        rs1 += __shfl_xor_sync(0xffffffffu, rs1, 1);
        rs1 += __shfl_xor_sync(0xffffffffu, rs1, 2);
        l0 = l0 * sc0 + rs0;
        l1 = l1 * sc1 + rs1;
        m0 = mn0; m1 = mn1;
        #pragma unroll
        for (int tn = 0; tn < 16; tn++) {
            oacc[tn][0] *= sc0; oacc[tn][1] *= sc0;
            oacc[tn][2] *= sc1; oacc[tn][3] *= sc1;
        }

        uint32_t pfrag[8][4];
        #pragma unroll
        for (int kg = 0; kg < 8; kg++) {
            pfrag[kg][0] = pack_half2(sacc[2 * kg][0], sacc[2 * kg][1]);
            pfrag[kg][1] = pack_half2(sacc[2 * kg][2], sacc[2 * kg][3]);
            pfrag[kg][2] = pack_half2(sacc[2 * kg + 1][0], sacc[2 * kg + 1][1]);
            pfrag[kg][3] = pack_half2(sacc[2 * kg + 1][2], sacc[2 * kg + 1][3]);
        }

        #pragma unroll
        for (int kg = 0; kg < 8; kg++) {
            int woff = (kg >> 1) * 20 + (kg & 1) * 8 + b_ksub;
            uint32_t bfr[16][2];
            #pragma unroll
            for (int tp = 0; tp < 8; tp++) {
                int row = tp * 16 + b_rsub;
                ldsm4(bfr[2 * tp][0], bfr[2 * tp][1],
                      bfr[2 * tp + 1][0], bfr[2 * tp + 1][1],
                      vs + row * FA_PITCH + woff);
            }
            #pragma unroll
            for (int tn = 0; tn < 16; tn++)
                mma_f16(oacc[tn], pfrag[kg], bfr[tn][0], bfr[tn][1]);
        }

        __syncthreads();
    }

    float inv0 = 1.f / l0, inv1 = 1.f / l1;
    __half* ar0 = ao + (size_t)(qb * 128 + wid * 16 + qd) * kH + head * kHD;
    __half* ar1 = ar0 + (size_t)8 * kH;
    #pragma unroll
    for (int tn = 0; tn < 16; tn++) {
        int col = tn * 8 + 2 * s;
        *(__half2*)(ar0 + col) = __floats2half2_rn(oacc[tn][0] * inv0, oacc[tn][1] * inv0);
        *(__half2*)(ar1 + col) = __floats2half2_rn(oacc[tn][2] * inv1, oacc[tn][3] * inv1);
    }
}

// ---------------- merged fp16 NT GEMM (ldmatrix, R12 core) ----------------
// Full-M launch; CTAs with yb < msplit use side-0 params, else side-1.
// A/C indexed by global row; res pointers pre-adjusted by caller so that
// res[row*ldc] is valid with the global row for each side.
constexpr int STAGES = 4;
constexpr int PITCHW = 20;
constexpr int TILE_W = 128 * PITCHW;
constexpr size_t GEMM_SMEM = (size_t)STAGES * 2 * TILE_W * 4;  // 81920

template <int EPI>
__global__ __launch_bounds__(128, 2) void gemm_m(
    const __half* __restrict__ A, int lda,
    const __half* __restrict__ B0, const __half* __restrict__ B1, int ldb,
    int msplit,
    void* __restrict__ Cv, int ldc,
    const float* __restrict__ bias0, const float* __restrict__ bias1,
    const float* __restrict__ gate0, const float* __restrict__ gate1,
    const float* __restrict__ res0, const float* __restrict__ res1,
    int K)
{
    int yb = blockIdx.y * 128;
    bool side = yb >= msplit;
    const __half* Ag = A + (size_t)yb * lda;
    const __half* Bg = (side ? B1 : B0) + (size_t)(blockIdx.x * 128) * ldb;
    const float* bias = side ? bias1 : bias0;
    const float* gate = side ? gate1 : gate0;
    const float* res  = side ? res1 : res0;
    float* Cf = (float*)Cv;
    __half* Ch = (__half*)Cv;

    extern __shared__ uint32_t smw[];
    uint32_t* As = smw;
    uint32_t* Bs = smw + STAGES * TILE_W;

    int tid  = threadIdx.x;
    int warp = tid >> 5, lane = tid & 31;
    int wm = warp >> 1, wn = warp & 1;
    int qd = lane >> 2, s = lane & 3;

    int frow = tid >> 2;
    int fc4  = (tid & 3) * 4;

    int a_row = wm * 64 + ((lane >> 3) & 1) * 8 + (lane & 7);
    int a_kw  = (lane >> 4) * 4;
    int b_row = wn * 64 + (lane >> 4) * 8 + (lane & 7);
    int b_kw  = ((lane >> 3) & 1) * 4;

    float acc[4][8][4] = {};
    int nk = K >> 5;

    auto prefetch = [&](int k0i, int st) {
        int kbase = k0i * 32 + (tid & 3) * 8;
        uint32_t* as = As + st * TILE_W;
        uint32_t* bs = Bs + st * TILE_W;
        #pragma unroll
        for (int i = 0; i < 4; i++) {
            int row = i * 32 + frow;
            cp16(as + row * PITCHW + fc4, Ag + (size_t)row * lda + kbase);
            cp16(bs + row * PITCHW + fc4, Bg + (size_t)row * ldb + kbase);
        }
    };

    #pragma unroll
    for (int st = 0; st < STAGES - 1; st++) {
        if (st < nk) prefetch(st, st);
        asm volatile("cp.async.commit_group;\n");
    }

    for (int k0i = 0; k0i < nk; k0i++) {
        asm volatile("cp.async.wait_group %0;\n" :: "n"(STAGES - 2));
        __syncthreads();

        const uint32_t* as = As + (k0i % STAGES) * TILE_W;
        const uint32_t* bs = Bs + (k0i % STAGES) * TILE_W;
        #pragma unroll
        for (int kg = 0; kg < 2; kg++) {
            int kw = kg * 8;
            uint32_t afr[4][4];
            #pragma unroll
            for (int tm = 0; tm < 4; tm++)
                ldsm4(afr[tm][0], afr[tm][1], afr[tm][2], afr[tm][3],
                      as + (a_row + tm * 16) * PITCHW + kw + a_kw);
            uint32_t bfr[8][2];
            #pragma unroll
            for (int tp = 0; tp < 4; tp++)
                ldsm4(bfr[2 * tp][0], bfr[2 * tp][1], bfr[2 * tp + 1][0], bfr[2 * tp + 1][1],
                      bs + (b_row + tp * 16) * PITCHW + kw + b_kw);
            #pragma unroll
            for (int tn = 0; tn < 8; tn++)
                #pragma unroll
                for (int tm = 0; tm < 4; tm++)
                    mma_f16(acc[tm][tn], afr[tm], bfr[tn][0], bfr[tn][1]);
        }

        int pf = k0i + STAGES - 1;
        if (pf < nk) prefetch(pf, pf % STAGES);
        asm volatile("cp.async.commit_group;\n");
    }

    int row_base = yb + wm * 64 + qd;
    int col_base = blockIdx.x * 128 + wn * 64;
    #pragma unroll
    for (int tm = 0; tm < 4; tm++) {
        #pragma unroll
        for (int tn = 0; tn < 8; tn++) {
            int col = col_base + tn * 8 + 2 * s;
            #pragma unroll
            for (int half = 0; half < 2; half++) {
                int row = row_base + tm * 16 + half * 8;
                float v0 = acc[tm][tn][half * 2 + 0];
                float v1 = acc[tm][tn][half * 2 + 1];
                if (EPI == 0) {
                    *(__half2*)&Ch[(size_t)row * ldc + col] = __floats2half2_rn(v0, v1);
                } else if (EPI == 1) {
                    v0 = gelu_tanh(v0 + bias[col]);
                    v1 = gelu_tanh(v1 + bias[col + 1]);
                    *(__half2*)&Ch[(size_t)row * ldc + col] = __floats2half2_rn(v0, v1);
                } else {
                    if (bias) { v0 += bias[col]; v1 += bias[col + 1]; }
                    const float* rp = res + (size_t)row * ldc + col;
                    v0 = rp[0] + gate[col] * v0;
                    v1 = rp[1] + gate[col + 1] * v1;
                    *(float2*)&Cf[(size_t)row * ldc + col] = make_float2(v0, v1);
                }
            }
        }
    }
}

// ---------------- launch ----------------
extern "C" void kernel_launch(void* const* d_in, const int* in_sizes, int n_in,
                              void* d_out, int out_size) {
    const float* txt           = (const float*)d_in[0];
    const float* img           = (const float*)d_in[1];
    const float* vec           = (const float*)d_in[2];
    const float* rope          = (const float*)d_in[3];
    const float* txt_adaln_w   = (const float*)d_in[4];
    const float* txt_adaln_b   = (const float*)d_in[5];
    const float* txt_adaln_rms = (const float*)d_in[6];
    const float* img_adaln_w   = (const float*)d_in[7];
    const float* img_adaln_b   = (const float*)d_in[8];
    const float* img_adaln_rms = (const float*)d_in[9];
    const float* txt_qkv_w     = (const float*)d_in[10];
    const float* img_qkv_w     = (const float*)d_in[11];
    const float* txt_out_w     = (const float*)d_in[12];
    const float* img_out_w     = (const float*)d_in[13];
    const float* txt_norm2_w   = (const float*)d_in[14];
    const float* img_norm2_w   = (const float*)d_in[15];
    const float* txt_fc1_w     = (const float*)d_in[16];
    const float* txt_fc1_b     = (const float*)d_in[17];
    const float* txt_fc2_w     = (const float*)d_in[18];
    const float* txt_fc2_b     = (const float*)d_in[19];
    const float* img_fc1_w     = (const float*)d_in[20];
    const float* img_fc1_b     = (const float*)d_in[21];
    const float* img_fc2_w     = (const float*)d_in[22];
    const float* img_fc2_b     = (const float*)d_in[23];
    float* out = (float*)d_out;
    (void)in_sizes; (void)n_in; (void)out_size;

    static cudaStream_t s1 = nullptr;
    static cudaEvent_t ev0, evq, evo, ev1w, ev2w;
    static bool init_done = false;
    if (!init_done) {
        cudaFuncSetAttribute((const void*)gemm_m<0>, cudaFuncAttributeMaxDynamicSharedMemorySize, (int)GEMM_SMEM);
        cudaFuncSetAttribute((const void*)gemm_m<1>, cudaFuncAttributeMaxDynamicSharedMemorySize, (int)GEMM_SMEM);
        cudaFuncSetAttribute((const void*)gemm_m<2>, cudaFuncAttributeMaxDynamicSharedMemorySize, (int)GEMM_SMEM);
        cudaFuncSetAttribute((const void*)flash_attn, cudaFuncAttributeMaxDynamicSharedMemorySize, (int)FA_SMEM);
        cudaStreamCreateWithFlags(&s1, cudaStreamNonBlocking);
        cudaEventCreateWithFlags(&ev0, cudaEventDisableTiming);
        cudaEventCreateWithFlags(&evq, cudaEventDisableTiming);
        cudaEventCreateWithFlags(&evo, cudaEventDisableTiming);
        cudaEventCreateWithFlags(&ev1w, cudaEventDisableTiming);
        cudaEventCreateWithFlags(&ev2w, cudaEventDisableTiming);
        init_done = true;
    }

    float* fs = nullptr;
    __half* hs = nullptr;
    cudaGetSymbolAddress((void**)&fs, g_scratch_f);
    cudaGetSymbolAddress((void**)&hs, g_scratch_h);
    float* silu = fs + FOFF_SILU;
    float* mod  = fs + FOFF_MOD;
    float* tmod = mod;
    float* imod = mod + 6 * kH;
    float* res  = fs + FOFF_RES;
    __half* xn  = hs + HOFF_XN;
    __half* qkv = hs + HOFF_QKV;
    __half* q   = hs + HOFF_Q;
    __half* k   = hs + HOFF_K;
    __half* vt  = hs + HOFF_VT;
    __half* ao  = hs + HOFF_AO;
    __half* h1  = hs + HOFF_H1;
    __half* wqt = hs + HOFF_WQT;
    __half* wqi = hs + HOFF_WQI;
    __half* wot = hs + HOFF_WOT;
    __half* woi = hs + HOFF_WOI;
    __half* w1t = hs + HOFF_W1T;
    __half* w1i = hs + HOFF_W1I;
    __half* w2t = hs + HOFF_W2T;
    __half* w2i = hs + HOFF_W2I;

    auto conv = [&](const float* src, __half* dst, size_t n, cudaStream_t st) {
        int n4 = (int)(n / 4);
        f2h<<<(n4 + 255) / 256, 256, 0, st>>>((const float4*)src, (__half2*)dst, n4);
    };

    // prelude on main; weight conversions on s1
    silu_kernel<<<8, 256>>>(vec, silu);
    cudaEventRecord(ev0, 0);
    cudaStreamWaitEvent(s1, ev0, 0);
    conv(txt_qkv_w, wqt, (size_t)3 * kH * kH, s1);
    conv(img_qkv_w, wqi, (size_t)3 * kH * kH, s1);
    cudaEventRecord(evq, s1);
    conv(txt_out_w, wot, (size_t)kH * kH, s1);
    conv(img_out_w, woi, (size_t)kH * kH, s1);
    cudaEventRecord(evo, s1);
    conv(txt_fc1_w, w1t, (size_t)kMLP * kH, s1);
    conv(img_fc1_w, w1i, (size_t)kMLP * kH, s1);
    cudaEventRecord(ev1w, s1);
    conv(txt_fc2_w, w2t, (size_t)kH * kMLP, s1);
    conv(img_fc2_w, w2i, (size_t)kH * kMLP, s1);
    cudaEventRecord(ev2w, s1);

    adaln_gemv<<<(2 * 6 * kH) / 8, 256>>>(silu, txt_adaln_w, txt_adaln_b,
                                          img_adaln_w, img_adaln_b, mod);

    // merged norm1 (txt rows 0-511, img rows 512-2559)
    norm_mod2<<<kSEQ, 256>>>(txt, img, xn,
                             txt_adaln_rms, img_adaln_rms,
                             tmod, tmod + kH, imod, imod + kH, kL);

    // merged QKV: 960 CTAs, deterministic packing
    cudaStreamWaitEvent(0, evq, 0);
    gemm_m<0><<<dim3(3 * kH / 128, kSEQ / 128), 128, GEMM_SMEM>>>(
        xn, kH, wqt, wqi, kH, kL, qkv, 3 * kH,
        nullptr, nullptr, nullptr, nullptr, nullptr, nullptr, kH);

    // RoPE + head scatter
    rope_scatter<<<(kSEQ * kHEADS * 64) / 256, 256>>>(qkv, rope, q, k, vt);

    // fused joint flash attention
    flash_attn<<<dim3(kSEQ / 128, kHEADS), 256, FA_SMEM>>>(q, k, vt, ao);

    // merged out-projection with gated residual (res1 adjusted for global-row indexing)
    cudaStreamWaitEvent(0, evo, 0);
    gemm_m<2><<<dim3(kH / 128, kSEQ / 128), 128, GEMM_SMEM>>>(
        ao, kH, wot, woi, kH, kL, res, kH,
        nullptr, nullptr, tmod + 2 * kH, imod + 2 * kH,
        txt, img - (size_t)kL * kH, kH);

    // merged norm2 (res is contiguous; x1 base offset so row-msplit works)
    norm_mod2<<<kSEQ, 256>>>(res, res + (size_t)kL * kH, xn,
                             txt_norm2_w, img_norm2_w,
                             tmod + 3 * kH, tmod + 4 * kH,
                             imod + 3 * kH, imod + 4 * kH, kL);

    // merged fc1 (gelu)
    cudaStreamWaitEvent(0, ev1w, 0);
    gemm_m<1><<<dim3(kMLP / 128, kSEQ / 128), 128, GEMM_SMEM>>>(
        xn, kH, w1t, w1i, kH, kL, h1, kMLP,
        txt_fc1_b, img_fc1_b, nullptr, nullptr, nullptr, nullptr, kH);

    // merged fc2 (gated residual -> out)
    cudaStreamWaitEvent(0, ev2w, 0);
    gemm_m<2><<<dim3(kH / 128, kSEQ / 128), 128, GEMM_SMEM>>>(
        h1, kMLP, w2t, w2i, kMLP, kL, out, kH,
        txt_fc2_b, img_fc2_b, tmod + 5 * kH, imod + 5 * kH,
        res, res, kMLP);
}

// round 16
// speedup vs baseline: 1.1901x; 1.1901x over previous
#include <cuda_runtime.h>
#include <cuda_fp16.h>
#include <math.h>
#include <stdint.h>

// ---------------- problem constants ----------------
constexpr int kH     = 2048;
constexpr int kL     = 512;
constexpr int kN     = 2048;
constexpr int kSEQ   = 2560;
constexpr int kHEADS = 16;
constexpr int kHD    = 128;
constexpr int kMLP   = 8192;
constexpr int kNSM   = 152;   // GB300 SM count

// ---------------- scratch (float + half pools, no allocs) ----------------
constexpr size_t FOFF_SILU = 0;
constexpr size_t FOFF_MOD  = FOFF_SILU + kH;
constexpr size_t FOFF_RES  = FOFF_MOD + (size_t)2 * 6 * kH;
constexpr size_t FTOT      = FOFF_RES + (size_t)kSEQ * kH;

constexpr size_t HOFF_XN   = 0;
constexpr size_t HOFF_QKV  = HOFF_XN  + (size_t)kSEQ * kH;
constexpr size_t HOFF_Q    = HOFF_QKV + (size_t)kSEQ * 3 * kH;
constexpr size_t HOFF_K    = HOFF_Q   + (size_t)kHEADS * kSEQ * kHD;
constexpr size_t HOFF_VT   = HOFF_K   + (size_t)kHEADS * kSEQ * kHD;
constexpr size_t HOFF_AO   = HOFF_VT  + (size_t)kHEADS * kHD * kSEQ;
constexpr size_t HOFF_H1   = HOFF_AO  + (size_t)kSEQ * kH;
constexpr size_t HOFF_H1T  = HOFF_H1  + (size_t)kN * kMLP;
constexpr size_t HOFF_WQT  = HOFF_H1T + (size_t)kL * kMLP;
constexpr size_t HOFF_WQI  = HOFF_WQT + (size_t)3 * kH * kH;
constexpr size_t HOFF_WOT  = HOFF_WQI + (size_t)3 * kH * kH;
constexpr size_t HOFF_WOI  = HOFF_WOT + (size_t)kH * kH;
constexpr size_t HOFF_W1T  = HOFF_WOI + (size_t)kH * kH;
constexpr size_t HOFF_W1I  = HOFF_W1T + (size_t)kMLP * kH;
constexpr size_t HOFF_W2T  = HOFF_W1I + (size_t)kMLP * kH;
constexpr size_t HOFF_W2I  = HOFF_W2T + (size_t)kH * kMLP;
constexpr size_t HTOT      = HOFF_W2I + (size_t)kH * kMLP;

__device__ __align__(256) float  g_scratch_f[FTOT];
__device__ __align__(256) __half g_scratch_h[HTOT];

// ---------------- small helper kernels ----------------
__global__ void silu_kernel(const float* __restrict__ vec, float* __restrict__ out) {
    int i = blockIdx.x * blockDim.x + threadIdx.x;
    if (i < kH) {
        float v = vec[i];
        out[i] = v / (1.f + expf(-v));
    }
}

__global__ void adaln_gemv(const float* __restrict__ silu,
                           const float* __restrict__ tw, const float* __restrict__ tb,
                           const float* __restrict__ iw, const float* __restrict__ ib,
                           float* __restrict__ mod) {
    int gw = (blockIdx.x * blockDim.x + threadIdx.x) >> 5;
    int lane = threadIdx.x & 31;
    if (gw >= 2 * 6 * kH) return;
    int set = gw / (6 * kH);
    int o = gw - set * (6 * kH);
    const float* W = (set ? iw : tw) + (size_t)o * kH;
    float s = 0.f;
    for (int i = lane; i < kH; i += 32) s += silu[i] * W[i];
    #pragma unroll
    for (int off = 16; off; off >>= 1) s += __shfl_xor_sync(0xffffffffu, s, off);
    if (lane == 0) mod[(size_t)set * 6 * kH + o] = s + (set ? ib[o] : tb[o]);
}

__global__ void f2h(const float4* __restrict__ in, __half2* __restrict__ out, int n4) {
    int i = blockIdx.x * blockDim.x + threadIdx.x;
    if (i >= n4) return;
    float4 v = in[i];
    out[2 * i + 0] = __floats2half2_rn(v.x, v.y);
    out[2 * i + 1] = __floats2half2_rn(v.z, v.w);
}

__global__ void norm_mod(const float* __restrict__ x, __half* __restrict__ out,
                         const float* __restrict__ w,
                         const float* __restrict__ sh, const float* __restrict__ sc) {
    int row = blockIdx.x;
    const float* xr = x + (size_t)row * kH;
    __half* orow = out + (size_t)row * kH;
    int tid = threadIdx.x;
    float ss = 0.f;
    for (int i = tid; i < kH; i += 256) { float v = xr[i]; ss += v * v; }
    __shared__ float sred[8];
    #pragma unroll
    for (int off = 16; off; off >>= 1) ss += __shfl_xor_sync(0xffffffffu, ss, off);
    if ((tid & 31) == 0) sred[tid >> 5] = ss;
    __syncthreads();
    if (tid < 8) {
        float v = sred[tid];
        #pragma unroll
        for (int off = 4; off; off >>= 1) v += __shfl_xor_sync(0xffu, v, off);
        if (tid == 0) sred[0] = v;
    }
    __syncthreads();
    float norm = rsqrtf(sred[0] * (1.f / kH) + 1e-6f);
    for (int i = tid; i < kH; i += 256)
        orow[i] = __float2half_rn(xr[i] * norm * w[i] * (1.f + sc[i]) + sh[i]);
}

__global__ void rope_scatter(const __half* __restrict__ qkv, const float* __restrict__ rope,
                             __half* __restrict__ q, __half* __restrict__ k,
                             __half* __restrict__ vt) {
    int gid = blockIdx.x * blockDim.x + threadIdx.x;
    if (gid >= kSEQ * kHEADS * (kHD / 2)) return;
    int j = gid & 63;
    int h = (gid >> 6) & 15;
    int n = gid >> 10;
    int d = j * 2;
    const float qscale = 0.08838834764831845f;
    const __half* base = qkv + (size_t)n * 3 * kH;
    float2 qv = __half22float2(*(const __half2*)(base + h * kHD + d));
    float2 kv = __half22float2(*(const __half2*)(base + kH + h * kHD + d));
    float2 vv = __half22float2(*(const __half2*)(base + 2 * kH + h * kHD + d));
    float q0 = qv.x, q1 = qv.y, k0 = kv.x, k1 = kv.y;
    if (n >= kL) {
        const float* r = rope + (size_t)(n - kL) * kHD + d;
        float c = r[0], s = r[1];
        float t;
        t = q0 * c - q1 * s; q1 = q1 * c + q0 * s; q0 = t;
        t = k0 * c - k1 * s; k1 = k1 * c + k0 * s; k0 = t;
    }
    size_t qi = ((size_t)h * kSEQ + n) * kHD + d;
    *(__half2*)(q + qi) = __floats2half2_rn(q0 * qscale, q1 * qscale);
    *(__half2*)(k + qi) = __floats2half2_rn(k0, k1);
    size_t vi = ((size_t)h * kHD + d) * kSEQ + n;
    vt[vi] = __float2half_rn(vv.x);
    vt[vi + kSEQ] = __float2half_rn(vv.y);
}

// ---------------- shared mma/ldmatrix/cp.async helpers ----------------
__device__ __forceinline__ float gelu_tanh(float x) {
    float x3 = x * x * x;
    return 0.5f * x * (1.f + tanhf(0.7978845608028654f * (x + 0.044715f * x3)));
}

__device__ __forceinline__ uint32_t pack_half2(float lo, float hi) {
    uint32_t r;
    asm("cvt.rn.f16x2.f32 %0, %1, %2;" : "=r"(r) : "f"(hi), "f"(lo));
    return r;
}

__device__ __forceinline__ void mma_f16(float c[4], const uint32_t a[4],
                                        uint32_t b0, uint32_t b1) {
    asm volatile(
        "mma.sync.aligned.m16n8k16.row.col.f32.f16.f16.f32 "
        "{%0,%1,%2,%3}, {%4,%5,%6,%7}, {%8,%9}, {%0,%1,%2,%3};\n"
        : "+f"(c[0]), "+f"(c[1]), "+f"(c[2]), "+f"(c[3])
        : "r"(a[0]), "r"(a[1]), "r"(a[2]), "r"(a[3]), "r"(b0), "r"(b1));
}

__device__ __forceinline__ void ldsm4(uint32_t& r0, uint32_t& r1, uint32_t& r2,
                                      uint32_t& r3, const uint32_t* p) {
    uint32_t a = (uint32_t)__cvta_generic_to_shared(p);
    asm volatile("ldmatrix.sync.aligned.m8n8.x4.shared.b16 {%0,%1,%2,%3}, [%4];\n"
                 : "=r"(r0), "=r"(r1), "=r"(r2), "=r"(r3) : "r"(a));
}

__device__ __forceinline__ void cp16(uint32_t* smem_dst, const void* gsrc) {
    uint32_t s = (uint32_t)__cvta_generic_to_shared(smem_dst);
    asm volatile("cp.async.cg.shared.global [%0], [%1], 16;\n" :: "r"(s), "l"(gsrc));
}

// ================= fused flash attention (persistent, 2 exact waves) ======
// grid = 2*kNSM CTAs; items = (qb, head) pairs, CTA i handles i, i+304, ...
constexpr int FA_PITCH = 84;
constexpr int FA_TILE  = 128 * FA_PITCH;
constexpr size_t FA_SMEM = (size_t)4 * FA_TILE * 4;  // 172032 B
constexpr int FA_ITEMS = (kSEQ / 128) * kHEADS;      // 320
constexpr int FA_GRID  = 2 * kNSM;                   // 304

__global__ __launch_bounds__(256, 1) void flash_attn(
    const __half* __restrict__ q, const __half* __restrict__ k,
    const __half* __restrict__ vt, __half* __restrict__ ao)
{
    extern __shared__ uint32_t sm[];
    uint32_t* Ks = sm;
    uint32_t* Vs = sm + 2 * FA_TILE;

    int tid = threadIdx.x, wid = tid >> 5, lane = tid & 31;
    int qd = lane >> 2, s = lane & 3;
    int b_rsub = ((lane >> 4) * 8) + (lane & 7);
    int b_ksub = ((lane >> 3) & 1) * 4;

    for (int item = blockIdx.x; item < FA_ITEMS; item += FA_GRID) {
        int qb = item % (kSEQ / 128);
        int head = item / (kSEQ / 128);

        const __half* kgb = k  + (size_t)head * kSEQ * kHD;
        const __half* vgb = vt + (size_t)head * kHD * kSEQ;

        const __half* qg = q + ((size_t)head * kSEQ + qb * 128 + wid * 16) * kHD;
        uint32_t qfrag[8][4];
        #pragma unroll
        for (int kg = 0; kg < 8; kg++) {
            qfrag[kg][0] = *(const uint32_t*)(qg + (size_t)qd * kHD + kg * 16 + 2 * s);
            qfrag[kg][1] = *(const uint32_t*)(qg + (size_t)(qd + 8) * kHD + kg * 16 + 2 * s);
            qfrag[kg][2] = *(const uint32_t*)(qg + (size_t)qd * kHD + kg * 16 + 8 + 2 * s);
            qfrag[kg][3] = *(const uint32_t*)(qg + (size_t)(qd + 8) * kHD + kg * 16 + 8 + 2 * s);
        }

        auto fill = [&](int j, int st) {
            const __half* kj = kgb + (size_t)j * 128 * kHD;
            const __half* vj = vgb + j * 128;
            uint32_t* ks = Ks + st * FA_TILE;
            uint32_t* vs = Vs + st * FA_TILE;
            #pragma unroll
            for (int i = 0; i < 8; i++) {
                int u = tid + i * 256;
                int row = u >> 4, w16 = u & 15;
                int sw = row * FA_PITCH + (w16 >> 2) * 20 + (w16 & 3) * 4;
                cp16(ks + sw, kj + (size_t)row * kHD + w16 * 8);
                cp16(vs + sw, vj + (size_t)row * kSEQ + w16 * 8);
            }
        };

        float oacc[16][4] = {};
        float m0 = -3.0e38f, m1 = -3.0e38f, l0 = 0.f, l1 = 0.f;

        fill(0, 0);
        asm volatile("cp.async.commit_group;\n");

        constexpr int NJ = kSEQ / 128;
        for (int j = 0; j < NJ; j++) {
            int st = j & 1;
            if (j + 1 < NJ) {
                fill(j + 1, st ^ 1);
                asm volatile("cp.async.commit_group;\n");
                asm volatile("cp.async.wait_group 1;\n");
            } else {
                asm volatile("cp.async.wait_group 0;\n");
            }
            __syncthreads();

            const uint32_t* ks = Ks + st * FA_TILE;
            const uint32_t* vs = Vs + st * FA_TILE;

            float sacc[16][4] = {};
            #pragma unroll
            for (int kg = 0; kg < 8; kg++) {
                int woff = (kg >> 1) * 20 + (kg & 1) * 8 + b_ksub;
                uint32_t bfr[16][2];
                #pragma unroll
                for (int tp = 0; tp < 8; tp++) {
                    int row = tp * 16 + b_rsub;
                    ldsm4(bfr[2 * tp][0], bfr[2 * tp][1],
                          bfr[2 * tp + 1][0], bfr[2 * tp + 1][1],
                          ks + row * FA_PITCH + woff);
                }
                #pragma unroll
                for (int tn = 0; tn < 16; tn++)
                    mma_f16(sacc[tn], qfrag[kg], bfr[tn][0], bfr[tn][1]);
            }

            float mb0 = -3.0e38f, mb1 = -3.0e38f;
            #pragma unroll
            for (int tn = 0; tn < 16; tn++) {
                mb0 = fmaxf(mb0, fmaxf(sacc[tn][0], sacc[tn][1]));
                mb1 = fmaxf(mb1, fmaxf(sacc[tn][2], sacc[tn][3]));
            }
            mb0 = fmaxf(mb0, __shfl_xor_sync(0xffffffffu, mb0, 1));
            mb0 = fmaxf(mb0, __shfl_xor_sync(0xffffffffu, mb0, 2));
            mb1 = fmaxf(mb1, __shfl_xor_sync(0xffffffffu, mb1, 1));
            mb1 = fmaxf(mb1, __shfl_xor_sync(0xffffffffu, mb1, 2));
            float mn0 = fmaxf(m0, mb0), mn1 = fmaxf(m1, mb1);
            float sc0 = __expf(m0 - mn0), sc1 = __expf(m1 - mn1);
            float rs0 = 0.f, rs1 = 0.f;
            #pragma unroll
            for (int tn = 0; tn < 16; tn++) {
                sacc[tn][0] = __expf(sacc[tn][0] - mn0);
                sacc[tn][1] = __expf(sacc[tn][1] - mn0);
                sacc[tn][2] = __expf(sacc[tn][2] - mn1);
                sacc[tn][3] = __expf(sacc[tn][3] - mn1);
                rs0 += sacc[tn][0] + sacc[tn][1];
                rs1 += sacc[tn][2] + sacc[tn][3];
            }
            rs0 += __shfl_xor_sync(0xffffffffu, rs0, 1);
            rs0 += __shfl_xor_sync(0xffffffffu, rs0, 2);
            rs1 += __shfl_xor_sync(0xffffffffu, rs1, 1);
            rs1 += __shfl_xor_sync(0xffffffffu, rs1, 2);
            l0 = l0 * sc0 + rs0;
            l1 = l1 * sc1 + rs1;
            m0 = mn0; m1 = mn1;
            #pragma unroll
            for (int tn = 0; tn < 16; tn++) {
                oacc[tn][0] *= sc0; oacc[tn][1] *= sc0;
                oacc[tn][2] *= sc1; oacc[tn][3] *= sc1;
            }

            uint32_t pfrag[8][4];
            #pragma unroll
            for (int kg = 0; kg < 8; kg++) {
                pfrag[kg][0] = pack_half2(sacc[2 * kg][0], sacc[2 * kg][1]);
                pfrag[kg][1] = pack_half2(sacc[2 * kg][2], sacc[2 * kg][3]);
                pfrag[kg][2] = pack_half2(sacc[2 * kg + 1][0], sacc[2 * kg + 1][1]);
                pfrag[kg][3] = pack_half2(sacc[2 * kg + 1][2], sacc[2 * kg + 1][3]);
            }

            #pragma unroll
            for (int kg = 0; kg < 8; kg++) {
                int woff = (kg >> 1) * 20 + (kg & 1) * 8 + b_ksub;
                uint32_t bfr[16][2];
                #pragma unroll
                for (int tp = 0; tp < 8; tp++) {
                    int row = tp * 16 + b_rsub;
                    ldsm4(bfr[2 * tp][0], bfr[2 * tp][1],
                          bfr[2 * tp + 1][0], bfr[2 * tp + 1][1],
                          vs + row * FA_PITCH + woff);
                }
                #pragma unroll
                for (int tn = 0; tn < 16; tn++)
                    mma_f16(oacc[tn], pfrag[kg], bfr[tn][0], bfr[tn][1]);
            }

            __syncthreads();
        }

        float inv0 = 1.f / l0, inv1 = 1.f / l1;
        __half* ar0 = ao + (size_t)(qb * 128 + wid * 16 + qd) * kH + head * kHD;
        __half* ar1 = ar0 + (size_t)8 * kH;
        #pragma unroll
        for (int tn = 0; tn < 16; tn++) {
            int col = tn * 8 + 2 * s;
            *(__half2*)(ar0 + col) = __floats2half2_rn(oacc[tn][0] * inv0, oacc[tn][1] * inv0);
            *(__half2*)(ar1 + col) = __floats2half2_rn(oacc[tn][2] * inv1, oacc[tn][3] * inv1);
        }
    }
}

// ---------------- pipelined fp16 tensor-core NT GEMM (R12 core) ----------
constexpr int STAGES = 4;
constexpr int PITCHW = 20;
constexpr int TILE_W = 128 * PITCHW;
constexpr size_t GEMM_SMEM = (size_t)STAGES * 2 * TILE_W * 4;  // 81920

template <int EPI>
__global__ __launch_bounds__(128, 2) void gemm_h(
    const __half* __restrict__ A, size_t sA,
    const __half* __restrict__ B, size_t sB,
    void* __restrict__ Cv, size_t sC, int ldc,
    int lda, int ldb,
    const float* __restrict__ bias,
    const float* __restrict__ gate,
    const float* __restrict__ res,
    int M, int N, int K)
{
    int yb = blockIdx.y * 128;
    const __half* Ag = A + (size_t)blockIdx.z * sA + (size_t)yb * lda;
    const __half* Bg = B + (size_t)blockIdx.z * sB + (size_t)(blockIdx.x * 128) * ldb;
    float* Cf = (float*)Cv + (size_t)blockIdx.z * sC;
    __half* Ch = (__half*)Cv + (size_t)blockIdx.z * sC;

    extern __shared__ uint32_t smw[];
    uint32_t* As = smw;
    uint32_t* Bs = smw + STAGES * TILE_W;

    int tid  = threadIdx.x;
    int warp = tid >> 5, lane = tid & 31;
    int wm = warp >> 1, wn = warp & 1;
    int qd = lane >> 2, s = lane & 3;

    int frow = tid >> 2;
    int fc4  = (tid & 3) * 4;

    int a_row = wm * 64 + ((lane >> 3) & 1) * 8 + (lane & 7);
    int a_kw  = (lane >> 4) * 4;
    int b_row = wn * 64 + (lane >> 4) * 8 + (lane & 7);
    int b_kw  = ((lane >> 3) & 1) * 4;

    float acc[4][8][4] = {};
    int nk = K >> 5;

    auto prefetch = [&](int k0i, int st) {
        int kbase = k0i * 32 + (tid & 3) * 8;
        uint32_t* as = As + st * TILE_W;
        uint32_t* bs = Bs + st * TILE_W;
        #pragma unroll
        for (int i = 0; i < 4; i++) {
            int row = i * 32 + frow;
            cp16(as + row * PITCHW + fc4, Ag + (size_t)row * lda + kbase);
            cp16(bs + row * PITCHW + fc4, Bg + (size_t)row * ldb + kbase);
        }
    };

    #pragma unroll
    for (int st = 0; st < STAGES - 1; st++) {
        if (st < nk) prefetch(st, st);
        asm volatile("cp.async.commit_group;\n");
    }

    for (int k0i = 0; k0i < nk; k0i++) {
        asm volatile("cp.async.wait_group %0;\n" :: "n"(STAGES - 2));
        __syncthreads();

        const uint32_t* as = As + (k0i % STAGES) * TILE_W;
        const uint32_t* bs = Bs + (k0i % STAGES) * TILE_W;
        #pragma unroll
        for (int kg = 0; kg < 2; kg++) {
            int kw = kg * 8;
            uint32_t afr[4][4];
            #pragma unroll
            for (int tm = 0; tm < 4; tm++)
                ldsm4(afr[tm][0], afr[tm][1], afr[tm][2], afr[tm][3],
                      as + (a_row + tm * 16) * PITCHW + kw + a_kw);
            uint32_t bfr[8][2];
            #pragma unroll
            for (int tp = 0; tp < 4; tp++)
                ldsm4(bfr[2 * tp][0], bfr[2 * tp][1], bfr[2 * tp + 1][0], bfr[2 * tp + 1][1],
                      bs + (b_row + tp * 16) * PITCHW + kw + b_kw);
            #pragma unroll
            for (int tn = 0; tn < 8; tn++)
                #pragma unroll
                for (int tm = 0; tm < 4; tm++)
                    mma_f16(acc[tm][tn], afr[tm], bfr[tn][0], bfr[tn][1]);
        }

        int pf = k0i + STAGES - 1;
        if (pf < nk) prefetch(pf, pf % STAGES);
        asm volatile("cp.async.commit_group;\n");
    }

    int row_base = yb + wm * 64 + qd;
    int col_base = blockIdx.x * 128 + wn * 64;
    #pragma unroll
    for (int tm = 0; tm < 4; tm++) {
        #pragma unroll
        for (int tn = 0; tn < 8; tn++) {
            int col = col_base + tn * 8 + 2 * s;
            #pragma unroll
            for (int half = 0; half < 2; half++) {
                int row = row_base + tm * 16 + half * 8;
                float v0 = acc[tm][tn][half * 2 + 0];
                float v1 = acc[tm][tn][half * 2 + 1];
                if (EPI == 0) {
                    *(__half2*)&Ch[(size_t)row * ldc + col] = __floats2half2_rn(v0, v1);
                } else if (EPI == 1) {
                    v0 = gelu_tanh(v0 + bias[col]);
                    v1 = gelu_tanh(v1 + bias[col + 1]);
                    *(__half2*)&Ch[(size_t)row * ldc + col] = __floats2half2_rn(v0, v1);
                } else {
                    if (bias) { v0 += bias[col]; v1 += bias[col + 1]; }
                    const float* rp = res + (size_t)row * ldc + col;
                    v0 = rp[0] + gate[col] * v0;
                    v1 = rp[1] + gate[col + 1] * v1;
                    *(float2*)&Cf[(size_t)row * ldc + col] = make_float2(v0, v1);
                }
            }
        }
    }
}

// ---------------- launch ----------------
extern "C" void kernel_launch(void* const* d_in, const int* in_sizes, int n_in,
                              void* d_out, int out_size) {
    const float* txt           = (const float*)d_in[0];
    const float* img           = (const float*)d_in[1];
    const float* vec           = (const float*)d_in[2];
    const float* rope          = (const float*)d_in[3];
    const float* txt_adaln_w   = (const float*)d_in[4];
    const float* txt_adaln_b   = (const float*)d_in[5];
    const float* txt_adaln_rms = (const float*)d_in[6];
    const float* img_adaln_w   = (const float*)d_in[7];
    const float* img_adaln_b   = (const float*)d_in[8];
    const float* img_adaln_rms = (const float*)d_in[9];
    const float* txt_qkv_w     = (const float*)d_in[10];
    const float* img_qkv_w     = (const float*)d_in[11];
    const float* txt_out_w     = (const float*)d_in[12];
    const float* img_out_w     = (const float*)d_in[13];
    const float* txt_norm2_w   = (const float*)d_in[14];
    const float* img_norm2_w   = (const float*)d_in[15];
    const float* txt_fc1_w     = (const float*)d_in[16];
    const float* txt_fc1_b     = (const float*)d_in[17];
    const float* txt_fc2_w     = (const float*)d_in[18];
    const float* txt_fc2_b     = (const float*)d_in[19];
    const float* img_fc1_w     = (const float*)d_in[20];
    const float* img_fc1_b     = (const float*)d_in[21];
    const float* img_fc2_w     = (const float*)d_in[22];
    const float* img_fc2_b     = (const float*)d_in[23];
    float* out = (float*)d_out;
    (void)in_sizes; (void)n_in; (void)out_size;

    static cudaStream_t s1 = nullptr;
    static cudaEvent_t ev0, ev1, ev2, ev3, ev4, evqi;
    static bool init_done = false;
    if (!init_done) {
        cudaFuncSetAttribute((const void*)gemm_h<0>, cudaFuncAttributeMaxDynamicSharedMemorySize, (int)GEMM_SMEM);
        cudaFuncSetAttribute((const void*)gemm_h<1>, cudaFuncAttributeMaxDynamicSharedMemorySize, (int)GEMM_SMEM);
        cudaFuncSetAttribute((const void*)gemm_h<2>, cudaFuncAttributeMaxDynamicSharedMemorySize, (int)GEMM_SMEM);
        cudaFuncSetAttribute((const void*)flash_attn, cudaFuncAttributeMaxDynamicSharedMemorySize, (int)FA_SMEM);
        cudaStreamCreateWithFlags(&s1, cudaStreamNonBlocking);
        cudaEventCreateWithFlags(&ev0, cudaEventDisableTiming);
        cudaEventCreateWithFlags(&ev1, cudaEventDisableTiming);
        cudaEventCreateWithFlags(&ev2, cudaEventDisableTiming);
        cudaEventCreateWithFlags(&ev3, cudaEventDisableTiming);
        cudaEventCreateWithFlags(&ev4, cudaEventDisableTiming);
        cudaEventCreateWithFlags(&evqi, cudaEventDisableTiming);
        init_done = true;
    }

    float* fs = nullptr;
    __half* hs = nullptr;
    cudaGetSymbolAddress((void**)&fs, g_scratch_f);
    cudaGetSymbolAddress((void**)&hs, g_scratch_h);
    float* silu = fs + FOFF_SILU;
    float* mod  = fs + FOFF_MOD;
    float* tmod = mod;
    float* imod = mod + 6 * kH;
    float* res  = fs + FOFF_RES;
    __half* xn  = hs + HOFF_XN;
    __half* qkv = hs + HOFF_QKV;
    __half* q   = hs + HOFF_Q;
    __half* k   = hs + HOFF_K;
    __half* vt  = hs + HOFF_VT;
    __half* ao  = hs + HOFF_AO;
    __half* h1  = hs + HOFF_H1;
    __half* h1t = hs + HOFF_H1T;
    __half* wqt = hs + HOFF_WQT;
    __half* wqi = hs + HOFF_WQI;
    __half* wot = hs + HOFF_WOT;
    __half* woi = hs + HOFF_WOI;
    __half* w1t = hs + HOFF_W1T;
    __half* w1i = hs + HOFF_W1I;
    __half* w2t = hs + HOFF_W2T;
    __half* w2i = hs + HOFF_W2I;

    auto conv = [&](const float* src, __half* dst, size_t n, cudaStream_t st) {
        int n4 = (int)(n / 4);
        f2h<<<(n4 + 255) / 256, 256, 0, st>>>((const float4*)src, (__half2*)dst, n4);
    };

    // adaLN modulation (fp32, main)
    silu_kernel<<<8, 256>>>(vec, silu);
    cudaEventRecord(ev0, 0);
    cudaStreamWaitEvent(s1, ev0, 0);

    // s1: img QKV weights first (frees main's critical path), then txt chain
    conv(img_qkv_w, wqi, (size_t)3 * kH * kH, s1);
    cudaEventRecord(evqi, s1);
    conv(txt_qkv_w, wqt, (size_t)3 * kH * kH, s1);

    adaln_gemv<<<(2 * 6 * kH) / 8, 256>>>(silu, txt_adaln_w, txt_adaln_b,
                                          img_adaln_w, img_adaln_b, mod);
    cudaEventRecord(ev2, 0);
    cudaStreamWaitEvent(s1, ev2, 0);     // s1 norm needs mod params

    norm_mod<<<kL, 256, 0, s1>>>(txt, xn, txt_adaln_rms, tmod, tmod + kH);
    gemm_h<0><<<dim3(3 * kH / 128, kL / 128), 128, GEMM_SMEM, s1>>>(
        xn, 0, wqt, 0, qkv, 0, 3 * kH, kH, kH,
        nullptr, nullptr, nullptr, kL, 3 * kH, kH);
    cudaEventRecord(ev1, s1);
    conv(txt_out_w, wot, (size_t)kH * kH, s1);
    conv(img_out_w, woi, (size_t)kH * kH, s1);
    conv(txt_fc1_w, w1t, (size_t)kMLP * kH, s1);
    conv(img_fc1_w, w1i, (size_t)kMLP * kH, s1);
    conv(txt_fc2_w, w2t, (size_t)kH * kMLP, s1);
    conv(img_fc2_w, w2i, (size_t)kH * kMLP, s1);
    cudaEventRecord(ev4, s1);

    norm_mod<<<kN, 256>>>(img, xn + (size_t)kL * kH, img_adaln_rms, imod, imod + kH);
    cudaStreamWaitEvent(0, evqi, 0);
    gemm_h<0><<<dim3(3 * kH / 128, kN / 128), 128, GEMM_SMEM>>>(
        xn + (size_t)kL * kH, 0, wqi, 0, qkv + (size_t)kL * 3 * kH, 0, 3 * kH,
        kH, kH, nullptr, nullptr, nullptr, kN, 3 * kH, kH);
    cudaStreamWaitEvent(0, ev1, 0);

    // RoPE + head scatter
    rope_scatter<<<(kSEQ * kHEADS * 64) / 256, 256>>>(qkv, rope, q, k, vt);

    // fused joint flash attention (persistent, 2 exact waves)
    flash_attn<<<dim3(FA_GRID), 256, FA_SMEM>>>(q, k, vt, ao);

    // ---- fork: txt tail on s1, img tail on main ----
    cudaEventRecord(ev2, 0);
    cudaStreamWaitEvent(s1, ev2, 0);
    cudaStreamWaitEvent(0, ev4, 0);

    // txt tail
    gemm_h<2><<<dim3(kH / 128, kL / 128), 128, GEMM_SMEM, s1>>>(
        ao, 0, wot, 0, res, 0, kH, kH, kH,
        nullptr, tmod + 2 * kH, txt, kL, kH, kH);
    norm_mod<<<kL, 256, 0, s1>>>(res, xn, txt_norm2_w, tmod + 3 * kH, tmod + 4 * kH);
    gemm_h<1><<<dim3(kMLP / 128, kL / 128), 128, GEMM_SMEM, s1>>>(
        xn, 0, w1t, 0, h1t, 0, kMLP, kH, kH,
        txt_fc1_b, nullptr, nullptr, kL, kMLP, kH);
    gemm_h<2><<<dim3(kH / 128, kL / 128), 128, GEMM_SMEM, s1>>>(
        h1t, 0, w2t, 0, out, 0, kH, kMLP, kMLP,
        txt_fc2_b, tmod + 5 * kH, res, kL, kH, kMLP);
    cudaEventRecord(ev3, s1);

    // img tail
    gemm_h<2><<<dim3(kH / 128, kN / 128), 128, GEMM_SMEM>>>(
        ao + (size_t)kL * kH, 0, woi, 0, res + (size_t)kL * kH, 0, kH, kH, kH,
        nullptr, imod + 2 * kH, img, kN, kH, kH);
    norm_mod<<<kN, 256>>>(res + (size_t)kL * kH, xn + (size_t)kL * kH,
                          img_norm2_w, imod + 3 * kH, imod + 4 * kH);
    gemm_h<1><<<dim3(kMLP / 128, kN / 128), 128, GEMM_SMEM>>>(
        xn + (size_t)kL * kH, 0, w1i, 0, h1, 0, kMLP, kH, kH,
        img_fc1_b, nullptr, nullptr, kN, kMLP, kH);
    gemm_h<2><<<dim3(kH / 128, kN / 128), 128, GEMM_SMEM>>>(
        h1, 0, w2i, 0, out + (size_t)kL * kH, 0, kH, kMLP, kMLP,
        img_fc2_b, imod + 5 * kH, res + (size_t)kL * kH, kN, kH, kMLP);

    cudaStreamWaitEvent(0, ev3, 0);
}